// round 2
// baseline (speedup 1.0000x reference)
#include <cuda_runtime.h>

// MultiDense: y[b,n,o] = sum_i x[b,n,i] * A[n,o,i] + Bp[n,o]
// x:  (2048, 256, 256) fp32
// A:  (1, 256, 256, 256) fp32   (n, o, i)
// Bp: (1, 256, 256) fp32        (n, o)  [broadcast over b]
// out:(2048, 256, 256) fp32

#define BSZ   2048
#define NSPL  256
#define DIN   256
#define DOUT  256

#define BM 64          // batch rows per block
#define BN 256         // full output dim per block (x read from DRAM exactly once)
#define BK 16
#define NSTAGE (DIN / BK)

// Xs row holds 64 x-values DUPLICATED (x0,x0,x1,x1,...) = 128 floats + pad.
// pitch*4 % 16 == 0 (LDS.128-able rows)
#define XPITCH 132
#define APITCH 260     // 256 + 4 pad

typedef unsigned long long ull;

__device__ __forceinline__ ull pack_dup(float v) {
    ull r; asm("mov.b64 %0, {%1, %1};" : "=l"(r) : "f"(v)); return r;
}
__device__ __forceinline__ void ffma2(ull& c, ull a, ull b) {
    // packed f32x2 FMA: c.lo += a.lo*b.lo ; c.hi += a.hi*b.hi  (2x FFMA throughput)
    asm("fma.rn.f32x2 %0, %1, %2, %0;" : "+l"(c) : "l"(a), "l"(b));
}
__device__ __forceinline__ float2 unpack2(ull v) {
    float2 r; asm("mov.b64 {%0, %1}, %2;" : "=f"(r.x), "=f"(r.y) : "l"(v)); return r;
}

__global__ __launch_bounds__(256, 2)
void multidense_kernel(const float* __restrict__ x,
                       const float* __restrict__ A,
                       const float* __restrict__ Bp,
                       float* __restrict__ out)
{
    __shared__ float Xs[BK][XPITCH];
    __shared__ float As[BK][APITCH];

    const int tid   = threadIdx.x;
    const int n     = blockIdx.y;            // group index
    const int mBase = blockIdx.x * BM;       // batch tile base
    const int tx    = tid & 31;              // output-fragment lane: o in {4tx..4tx+3, 128+4tx..+3}
    const int ty    = tid >> 5;              // m fragment: rows ty*8 .. ty*8+7
    const int lr    = tid >> 2;              // loader row 0..63
    const int lq    = tid & 3;               // loader quad (k sub-chunk)

    const float* xg = x + (size_t)(mBase + lr) * (NSPL * DIN) + (size_t)n * DIN + lq * 4;
    const float* Ag = A + (size_t)n * (DOUT * DIN) + (size_t)lr * DIN + lq * 4;

    ull acc[8][4];
    #pragma unroll
    for (int m = 0; m < 8; ++m) {
        acc[m][0] = 0ULL; acc[m][1] = 0ULL; acc[m][2] = 0ULL; acc[m][3] = 0ULL;
    }

    // prefetch stage 0 into registers
    float4 xr  = *(const float4*)(xg);
    float4 ar0 = *(const float4*)(Ag);
    float4 ar1 = *(const float4*)(Ag +  64 * DIN);
    float4 ar2 = *(const float4*)(Ag + 128 * DIN);
    float4 ar3 = *(const float4*)(Ag + 192 * DIN);

    for (int s = 0; s < NSTAGE; ++s) {
        __syncthreads();   // previous stage's reads done before overwrite

        // ---- stores: X duplicated as (x,x) pairs, A transposed to [k][o] ----
        *(ull*)&Xs[lq*4 + 0][2*lr] = pack_dup(xr.x);
        *(ull*)&Xs[lq*4 + 1][2*lr] = pack_dup(xr.y);
        *(ull*)&Xs[lq*4 + 2][2*lr] = pack_dup(xr.z);
        *(ull*)&Xs[lq*4 + 3][2*lr] = pack_dup(xr.w);

        As[lq*4 + 0][lr      ] = ar0.x;  As[lq*4 + 1][lr      ] = ar0.y;
        As[lq*4 + 2][lr      ] = ar0.z;  As[lq*4 + 3][lr      ] = ar0.w;
        As[lq*4 + 0][lr +  64] = ar1.x;  As[lq*4 + 1][lr +  64] = ar1.y;
        As[lq*4 + 2][lr +  64] = ar1.z;  As[lq*4 + 3][lr +  64] = ar1.w;
        As[lq*4 + 0][lr + 128] = ar2.x;  As[lq*4 + 1][lr + 128] = ar2.y;
        As[lq*4 + 2][lr + 128] = ar2.z;  As[lq*4 + 3][lr + 128] = ar2.w;
        As[lq*4 + 0][lr + 192] = ar3.x;  As[lq*4 + 1][lr + 192] = ar3.y;
        As[lq*4 + 2][lr + 192] = ar3.z;  As[lq*4 + 3][lr + 192] = ar3.w;

        __syncthreads();

        // ---- prefetch next stage (overlaps with compute below) ----
        if (s + 1 < NSTAGE) {
            const int ks = (s + 1) * BK;
            xr  = *(const float4*)(xg + ks);
            ar0 = *(const float4*)(Ag + ks);
            ar1 = *(const float4*)(Ag +  64 * DIN + ks);
            ar2 = *(const float4*)(Ag + 128 * DIN + ks);
            ar3 = *(const float4*)(Ag + 192 * DIN + ks);
        }

        // ---- compute: 16 k-steps x 8m x 8o, all FFMA2 ----
        #pragma unroll
        for (int k = 0; k < BK; ++k) {
            ull xp[8];
            #pragma unroll
            for (int h = 0; h < 4; ++h) {
                // LDS.128 of duplicated pairs -> two packed (x_m, x_m) operands, no MOVs
                ulonglong2 v = *(const ulonglong2*)&Xs[k][ty*16 + 4*h];
                xp[2*h]     = v.x;
                xp[2*h + 1] = v.y;
            }
            ulonglong2 a0 = *(const ulonglong2*)&As[k][tx*4];
            ulonglong2 a1 = *(const ulonglong2*)&As[k][128 + tx*4];
            ull ap[4] = {a0.x, a0.y, a1.x, a1.y};

            #pragma unroll
            for (int m = 0; m < 8; ++m) {
                ffma2(acc[m][0], xp[m], ap[0]);
                ffma2(acc[m][1], xp[m], ap[1]);
                ffma2(acc[m][2], xp[m], ap[2]);
                ffma2(acc[m][3], xp[m], ap[3]);
            }
        }
    }

    // ---- epilogue: bias add + store (coalesced float4, o = 4tx and 128+4tx) ----
    const float4 b0 = *(const float4*)(Bp + (size_t)n * DOUT + 4*tx);
    const float4 b1 = *(const float4*)(Bp + (size_t)n * DOUT + 128 + 4*tx);

    #pragma unroll
    for (int m = 0; m < 8; ++m) {
        float2 v0 = unpack2(acc[m][0]);
        float2 v1 = unpack2(acc[m][1]);
        float2 v2 = unpack2(acc[m][2]);
        float2 v3 = unpack2(acc[m][3]);
        float4 o0 = make_float4(v0.x + b0.x, v0.y + b0.y, v1.x + b0.z, v1.y + b0.w);
        float4 o1 = make_float4(v2.x + b1.x, v2.y + b1.y, v3.x + b1.z, v3.y + b1.w);
        float* og = out + (size_t)(mBase + ty*8 + m) * (NSPL * DOUT) + (size_t)n * DOUT + 4*tx;
        *(float4*)og         = o0;
        *(float4*)(og + 128) = o1;
    }
}

extern "C" void kernel_launch(void* const* d_in, const int* in_sizes, int n_in,
                              void* d_out, int out_size)
{
    const float* x  = (const float*)d_in[0];
    const float* A  = (const float*)d_in[1];
    const float* Bp = (const float*)d_in[2];
    float* out = (float*)d_out;

    dim3 grid(BSZ / BM, NSPL);   // (32, 256) = 8192 blocks
    multidense_kernel<<<grid, 256>>>(x, A, Bp, out);
}